// round 3
// baseline (speedup 1.0000x reference)
#include <cuda_runtime.h>

// Problem constants (fixed by the reference)
#define BB 16
#define TT 4096
#define DD 64
#define KK 1024
#define NROWS (BB * TT)           // 65536 rows
#define BETA_ 0.25

// Tiling
#define TK 64                     // codes per SMEM tile (64*64*4B = 16KB)
#define NTILES (KK / TK)          // 16
#define THREADS 64                // threads per block
#define RPT 2                     // rows per thread
#define ROWS_PER_BLOCK (THREADS * RPT)          // 128
#define NBLOCKS (NROWS / ROWS_PER_BLOCK)        // 512

// Scratch (no allocations allowed in kernel_launch)
__device__ float  g_ne[KK];
__device__ double g_partials[NBLOCKS];

// Packed fp32x2 FMA (Blackwell FFMA2): two IEEE fp32 FMAs per instruction.
__device__ __forceinline__ unsigned long long ffma2(unsigned long long a,
                                                    unsigned long long b,
                                                    unsigned long long c) {
    unsigned long long d;
    asm("fma.rn.f32x2 %0, %1, %2, %3;" : "=l"(d) : "l"(a), "l"(b), "l"(c));
    return d;
}

__device__ __forceinline__ void unpack2(unsigned long long v, float& lo, float& hi) {
    asm("mov.b64 {%0, %1}, %2;" : "=f"(lo), "=f"(hi) : "l"(v));
}

// --- Kernel 0: per-code squared norms  ne[k] = sum_i e[k,i]^2 -------------
__global__ void ne_kernel(const float* __restrict__ emb) {
    int k = blockIdx.x * blockDim.x + threadIdx.x;
    if (k < KK) {
        const float* e = emb + k * DD;
        float s0 = 0.f, s1 = 0.f, s2 = 0.f, s3 = 0.f;
        #pragma unroll
        for (int i = 0; i < DD; i += 4) {
            s0 = fmaf(e[i + 0], e[i + 0], s0);
            s1 = fmaf(e[i + 1], e[i + 1], s1);
            s2 = fmaf(e[i + 2], e[i + 2], s2);
            s3 = fmaf(e[i + 3], e[i + 3], s3);
        }
        g_ne[k] = (s0 + s1) + (s2 + s3);
    }
}

// --- Kernel 1: argmin over codebook + z_q gather + loss partials ----------
// Each thread owns RPT=2 rows in registers; the broadcast e-tile LDS stream
// is amortized across both rows (halves LDS per FMA vs R2).
__global__ void __launch_bounds__(THREADS)
vq_kernel(const float* __restrict__ z,
          const float* __restrict__ emb,
          float* __restrict__ out) {
    __shared__ __align__(16) float se[TK * DD];  // 16 KB codebook tile
    __shared__ float  sne[TK];                   // ne tile (broadcast LDS)
    __shared__ double sred[2];

    const int r0 = blockIdx.x * ROWS_PER_BLOCK + threadIdx.x;  // rows coalesced
    const int r1 = r0 + THREADS;

    // Load both z rows (64 floats each) as packed f32x2 values.
    unsigned long long zp0[32], zp1[32];
    {
        const ulonglong2* za =
            reinterpret_cast<const ulonglong2*>(z + (size_t)r0 * DD);
        const ulonglong2* zb =
            reinterpret_cast<const ulonglong2*>(z + (size_t)r1 * DD);
        #pragma unroll
        for (int i = 0; i < 16; i++) {
            ulonglong2 va = za[i];
            zp0[2 * i + 0] = va.x;  zp0[2 * i + 1] = va.y;
        }
        #pragma unroll
        for (int i = 0; i < 16; i++) {
            ulonglong2 vb = zb[i];
            zp1[2 * i + 0] = vb.x;  zp1[2 * i + 1] = vb.y;
        }
    }

    // ||z||^2 per row (bitwise == previous rounds' 4-way split)
    float nz0, nz1;
    {
        unsigned long long a01 = 0ull, a23 = 0ull, b01 = 0ull, b23 = 0ull;
        #pragma unroll
        for (int i = 0; i < 16; i++) {
            a01 = ffma2(zp0[2 * i + 0], zp0[2 * i + 0], a01);
            a23 = ffma2(zp0[2 * i + 1], zp0[2 * i + 1], a23);
            b01 = ffma2(zp1[2 * i + 0], zp1[2 * i + 0], b01);
            b23 = ffma2(zp1[2 * i + 1], zp1[2 * i + 1], b23);
        }
        float s0, s1, s2, s3;
        unpack2(a01, s0, s1); unpack2(a23, s2, s3);
        nz0 = (s0 + s1) + (s2 + s3);
        unpack2(b01, s0, s1); unpack2(b23, s2, s3);
        nz1 = (s0 + s1) + (s2 + s3);
    }

    float best0 = 3.4e38f, best1 = 3.4e38f;
    int   bidx0 = 0,       bidx1 = 0;

    for (int t = 0; t < NTILES; ++t) {
        __syncthreads();  // protect previous tile consumers
        // Cooperative tile load: 64 codes * 64 floats = 1024 float4
        {
            const float4* src =
                reinterpret_cast<const float4*>(emb) + t * (TK * DD / 4);
            float4* dst = reinterpret_cast<float4*>(se);
            #pragma unroll
            for (int i = 0; i < (TK * DD / 4) / THREADS; i++)
                dst[threadIdx.x + i * THREADS] = src[threadIdx.x + i * THREADS];
            sne[threadIdx.x] = g_ne[t * TK + threadIdx.x];
        }
        __syncthreads();

        #pragma unroll 2
        for (int k = 0; k < TK; k++) {
            const ulonglong2* e2 =
                reinterpret_cast<const ulonglong2*>(se + k * DD);
            unsigned long long a01 = 0ull, a23 = 0ull;  // row 0 chains
            unsigned long long b01 = 0ull, b23 = 0ull;  // row 1 chains
            #pragma unroll
            for (int i = 0; i < 16; i++) {
                ulonglong2 ev = e2[i];   // warp-uniform -> LDS broadcast
                a01 = ffma2(zp0[2 * i + 0], ev.x, a01);
                a23 = ffma2(zp0[2 * i + 1], ev.y, a23);
                b01 = ffma2(zp1[2 * i + 0], ev.x, b01);
                b23 = ffma2(zp1[2 * i + 1], ev.y, b23);
            }
            float ne_k = sne[k];
            int   gk   = t * TK + k;

            float d0, d1, d2, d3;
            unpack2(a01, d0, d1); unpack2(a23, d2, d3);
            float dot0  = (d0 + d1) + (d2 + d3);
            float dist0 = fmaf(-2.f, dot0, nz0 + ne_k);
            if (dist0 < best0) { best0 = dist0; bidx0 = gk; }

            unpack2(b01, d0, d1); unpack2(b23, d2, d3);
            float dot1  = (d0 + d1) + (d2 + d3);
            float dist1 = fmaf(-2.f, dot1, nz1 + ne_k);
            if (dist1 < best1) { best1 = dist1; bidx1 = gk; }
        }
    }

    // idx outputs (as float, output buffer is fp32)
    out[(size_t)NROWS * DD + 1 + r0] = (float)bidx0;
    out[(size_t)NROWS * DD + 1 + r1] = (float)bidx1;

    // z_q = emb[bidx] gather (bitwise-exact vs reference) + loss partial
    double acc = 0.0;
    {
        const float4* eg = reinterpret_cast<const float4*>(emb) + bidx0 * (DD / 4);
        const float*  zr = z + (size_t)r0 * DD;
        float4* oq = reinterpret_cast<float4*>(out) + r0 * (DD / 4);
        #pragma unroll
        for (int i = 0; i < 16; i++) {
            float4 ev = __ldg(&eg[i]);
            float dx = ev.x - zr[4 * i + 0];
            float dy = ev.y - zr[4 * i + 1];
            float dzc = ev.z - zr[4 * i + 2];
            float dw = ev.w - zr[4 * i + 3];
            acc += (double)dx * dx + (double)dy * dy
                 + (double)dzc * dzc + (double)dw * dw;
            oq[i] = ev;
        }
    }
    {
        const float4* eg = reinterpret_cast<const float4*>(emb) + bidx1 * (DD / 4);
        const float*  zr = z + (size_t)r1 * DD;
        float4* oq = reinterpret_cast<float4*>(out) + r1 * (DD / 4);
        #pragma unroll
        for (int i = 0; i < 16; i++) {
            float4 ev = __ldg(&eg[i]);
            float dx = ev.x - zr[4 * i + 0];
            float dy = ev.y - zr[4 * i + 1];
            float dzc = ev.z - zr[4 * i + 2];
            float dw = ev.w - zr[4 * i + 3];
            acc += (double)dx * dx + (double)dy * dy
                 + (double)dzc * dzc + (double)dw * dw;
            oq[i] = ev;
        }
    }

    // Deterministic in-block reduction (fixed shuffle tree + fixed order)
    #pragma unroll
    for (int o = 16; o > 0; o >>= 1)
        acc += __shfl_down_sync(0xffffffffu, acc, o);
    int lane = threadIdx.x & 31, w = threadIdx.x >> 5;
    if (lane == 0) sred[w] = acc;
    __syncthreads();
    if (threadIdx.x == 0) g_partials[blockIdx.x] = sred[0] + sred[1];
}

// --- Kernel 2: deterministic fixed-tree reduction of loss partials --------
__global__ void loss_kernel(float* __restrict__ out) {
    __shared__ double sd[256];
    int tid = threadIdx.x;  // 256 threads, NBLOCKS = 512 partials
    double s = g_partials[tid] + g_partials[tid + 256];
    sd[tid] = s;
    __syncthreads();
    #pragma unroll
    for (int st = 128; st > 0; st >>= 1) {
        if (tid < st) sd[tid] += sd[tid + st];
        __syncthreads();
    }
    if (tid == 0) {
        // loss = sum_b (beta*mean_b + mean_b) = 1.25 * total / (T*D)
        out[(size_t)NROWS * DD] =
            (float)((1.0 + BETA_) * sd[0] / (double)(TT * DD));
    }
}

extern "C" void kernel_launch(void* const* d_in, const int* in_sizes, int n_in,
                              void* d_out, int out_size) {
    const float* z   = (const float*)d_in[0];   // [B, T, D] fp32
    const float* emb = (const float*)d_in[1];   // [K, D]    fp32
    float* out = (float*)d_out;                 // [z_q | loss | idx] fp32

    ne_kernel<<<KK / 64, 64>>>(emb);
    vq_kernel<<<NBLOCKS, THREADS>>>(z, emb, out);
    loss_kernel<<<1, 256>>>(out);
}